// round 17
// baseline (speedup 1.0000x reference)
#include <cuda_runtime.h>
#include <cuda_bf16.h>

#define B       2
#define NV      16384
#define MOBS    12000
#define NF      16384
#define NCHUNK  16
#define FPC     (NF / NCHUNK)   // 1024 faces per chunk == one smem tile
#define T2      256             // threads; each handles 4 vertices
#define VPC     (T2 * 4)        // vertices per CTA = 1024
#define FLT_BIG 3.4e38f

typedef unsigned long long u64;

// ---- device scratch (no allocations allowed) ----
__device__ float4 g_fc[B * NF];            // (cx, cy, cz, |c|^2 fma-chain)
__device__ float4 g_fn[B * NF];            // next centroid (xyz)
__device__ float4 g_nm[B * NF];            // next normal (xyz, normalized)
__device__ float  g_best[NCHUNK][B * NV];  // per-chunk min exact score
__device__ int    g_bidx[NCHUNK][B * NV];  // per-chunk argmin face idx
__device__ float  g_partial[64];

// norm^2 with fma contraction, ascending (the critical rounding form)
__device__ __forceinline__ float norm2_fma(float x, float y, float z) {
    return __fmaf_rn(z, z, __fmaf_rn(y, y, __fmul_rn(x, x)));
}

// ---- packed f32x2 helpers (each lane is an independent IEEE fp32 rn op,
//      bit-identical to the scalar sequence) ----
__device__ __forceinline__ u64 pack2(float lo, float hi) {
    u64 r; asm("mov.b64 %0, {%1, %2};" : "=l"(r) : "f"(lo), "f"(hi)); return r;
}
__device__ __forceinline__ void unpack2(u64 v, float& lo, float& hi) {
    asm("mov.b64 {%0, %1}, %2;" : "=f"(lo), "=f"(hi) : "l"(v));
}
__device__ __forceinline__ u64 mul2(u64 a, u64 b) {
    u64 r; asm("mul.rn.f32x2 %0, %1, %2;" : "=l"(r) : "l"(a), "l"(b)); return r;
}
__device__ __forceinline__ u64 add2(u64 a, u64 b) {
    u64 r; asm("add.rn.f32x2 %0, %1, %2;" : "=l"(r) : "l"(a), "l"(b)); return r;
}
__device__ __forceinline__ u64 fma2(u64 a, u64 b, u64 c) {
    u64 r; asm("fma.rn.f32x2 %0, %1, %2, %3;" : "=l"(r) : "l"(a), "l"(b), "l"(c)); return r;
}

// ---------------------------------------------------------------------------
// Kernel 1: per (batch,face) preprocessing (R13-identical rounding).
// ---------------------------------------------------------------------------
__global__ void prep_kernel(const float* __restrict__ obs_c,
                            const float* __restrict__ obs_n,
                            const int* __restrict__ faces32) {
    __shared__ int s_is64;
    if (threadIdx.x == 0) {
        int orv = 0;
        #pragma unroll
        for (int j = 0; j < 64; ++j) orv |= faces32[2 * j + 1];
        s_is64 = (orv == 0) ? 1 : 0;
    }
    __syncthreads();

    int t = blockIdx.x * blockDim.x + threadIdx.x;
    if (t >= B * NF) return;
    int b = t / NF;

    int i0, i1, i2;
    if (s_is64) {
        i0 = faces32[t * 6 + 0]; i1 = faces32[t * 6 + 2]; i2 = faces32[t * 6 + 4];
    } else {
        i0 = faces32[t * 3 + 0]; i1 = faces32[t * 3 + 1]; i2 = faces32[t * 3 + 2];
    }
    i0 = min(max(i0, 0), MOBS - 1);
    i1 = min(max(i1, 0), MOBS - 1);
    i2 = min(max(i2, 0), MOBS - 1);

    const float* oc = obs_c + (long long)b * MOBS * 3;
    const float* on = obs_n + (long long)b * MOBS * 3;

    float cx = __fdiv_rn(__fadd_rn(__fadd_rn(oc[i0*3+0], oc[i1*3+0]), oc[i2*3+0]), 3.0f);
    float cy = __fdiv_rn(__fadd_rn(__fadd_rn(oc[i0*3+1], oc[i1*3+1]), oc[i2*3+1]), 3.0f);
    float cz = __fdiv_rn(__fadd_rn(__fadd_rn(oc[i0*3+2], oc[i1*3+2]), oc[i2*3+2]), 3.0f);
    g_fc[t] = make_float4(cx, cy, cz, norm2_fma(cx, cy, cz));

    float ax = on[i0*3+0], ay = on[i0*3+1], az = on[i0*3+2];
    float bx = on[i1*3+0], by = on[i1*3+1], bz = on[i1*3+2];
    float dx = on[i2*3+0], dy = on[i2*3+1], dz = on[i2*3+2];

    g_fn[t] = make_float4(
        __fdiv_rn(__fadd_rn(__fadd_rn(ax, bx), dx), 3.0f),
        __fdiv_rn(__fadd_rn(__fadd_rn(ay, by), dy), 3.0f),
        __fdiv_rn(__fadd_rn(__fadd_rn(az, bz), dz), 3.0f), 0.0f);

    float e1x = __fsub_rn(bx, ax), e1y = __fsub_rn(by, ay), e1z = __fsub_rn(bz, az);
    float e2x = __fsub_rn(dx, ax), e2y = __fsub_rn(dy, ay), e2z = __fsub_rn(dz, az);
    float nx = __fmaf_rn(e1y, e2z, -__fmul_rn(e1z, e2y));
    float ny = __fmaf_rn(e1z, e2x, -__fmul_rn(e1x, e2z));
    float nz = __fmaf_rn(e1x, e2y, -__fmul_rn(e1y, e2x));
    float nrm = __fadd_rn(__fsqrt_rn(norm2_fma(nx, ny, nz)), 1e-12f);
    g_nm[t] = make_float4(__fdiv_rn(nx, nrm), __fdiv_rn(ny, nrm),
                          __fdiv_rn(nz, nrm), 0.0f);
}

// ---------------------------------------------------------------------------
// Kernel 2: 1-NN argmin, packed f32x2 exact score, 4 vertices/thread.
// Score per lane (bit-identical to R13):
//   dot = fma(cz,fz, fma(cy,fy, rn(cx*fx)));  s = rn(fma(-2,dot,cn) + fw)
// smem tile stores faces pre-duplicated: [2j]=(fx,fx,fy,fy) [2j+1]=(fz,fz,fw,fw)
// ---------------------------------------------------------------------------
__global__ __launch_bounds__(T2) void nn_kernel(const float* __restrict__ cloth_c) {
    __shared__ float4 shd[2 * FPC];   // 32 KB

    int b     = blockIdx.y;
    int chunk = blockIdx.z;
    int nbase = blockIdx.x * VPC + threadIdx.x;

    // load 4 vertices: A=nbase, B=+256, C=+512, D=+768
    float vx[4], vy[4], vz[4], vn[4];
    #pragma unroll
    for (int k = 0; k < 4; ++k) {
        const float* cp = cloth_c + ((long long)b * NV + nbase + k * T2) * 3;
        vx[k] = cp[0]; vy[k] = cp[1]; vz[k] = cp[2];
        vn[k] = norm2_fma(vx[k], vy[k], vz[k]);
    }
    u64 cxAB = pack2(vx[0], vx[1]), cyAB = pack2(vy[0], vy[1]);
    u64 czAB = pack2(vz[0], vz[1]), cnAB = pack2(vn[0], vn[1]);
    u64 cxCD = pack2(vx[2], vx[3]), cyCD = pack2(vy[2], vy[3]);
    u64 czCD = pack2(vz[2], vz[3]), cnCD = pack2(vn[2], vn[3]);
    u64 m2   = pack2(-2.0f, -2.0f);

    int fbase = chunk * FPC;
    const float4* fc = g_fc + b * NF + fbase;
    for (int i = threadIdx.x; i < FPC; i += T2) {
        float4 f = fc[i];
        shd[2 * i + 0] = make_float4(f.x, f.x, f.y, f.y);
        shd[2 * i + 1] = make_float4(f.z, f.z, f.w, f.w);
    }
    __syncthreads();

    float best[4] = {FLT_BIG, FLT_BIG, FLT_BIG, FLT_BIG};
    int   bidx[4] = {0x7fffffff, 0x7fffffff, 0x7fffffff, 0x7fffffff};

    const ulonglong2* shq = (const ulonglong2*)shd;

    #pragma unroll 4
    for (int j = 0; j < FPC; ++j) {
        ulonglong2 q0 = shq[2 * j + 0];   // .x=(fx,fx) .y=(fy,fy)
        ulonglong2 q1 = shq[2 * j + 1];   // .x=(fz,fz) .y=(fw,fw)

        u64 dAB = fma2(czAB, q1.x, fma2(cyAB, q0.y, mul2(cxAB, q0.x)));
        u64 sAB = add2(fma2(m2, dAB, cnAB), q1.y);
        u64 dCD = fma2(czCD, q1.x, fma2(cyCD, q0.y, mul2(cxCD, q0.x)));
        u64 sCD = add2(fma2(m2, dCD, cnCD), q1.y);

        float s0, s1, s2, s3;
        unpack2(sAB, s0, s1);
        unpack2(sCD, s2, s3);
        int oi = fbase + j;
        if (s0 < best[0]) { best[0] = s0; bidx[0] = oi; }  // strict < ->
        if (s1 < best[1]) { best[1] = s1; bidx[1] = oi; }  // first occurrence
        if (s2 < best[2]) { best[2] = s2; bidx[2] = oi; }
        if (s3 < best[3]) { best[3] = s3; bidx[3] = oi; }
    }
    #pragma unroll
    for (int k = 0; k < 4; ++k) {
        g_best[chunk][b * NV + nbase + k * T2] = best[k];
        g_bidx[chunk][b * NV + nbase + k * T2] = bidx[k];
    }
}

// ---------------------------------------------------------------------------
// Kernel 3: merge chunks by (exact s, idx) lexicographic (== reference's
// first-index argmin), then plane distance / interpenetration / weight.
// ---------------------------------------------------------------------------
__global__ void epi_kernel(const float* __restrict__ cloth_n,
                           const int* __restrict__ iterp,
                           float* __restrict__ out) {
    int n = blockIdx.x * blockDim.x + threadIdx.x;

    int iter = iterp ? iterp[0] : 60000;  // low word valid for LE int64 too
    int it = iter - 50000; if (it < 0) it = 0;
    double prog = (double)it / 100000.0;
    if (prog > 1.0) prog = 1.0;
    float weight = (float)(1e-3 + (5e3 - 1e-3) * prog);

    float val = 0.0f;
    if (n < NV) {
        float acc = 0.0f;
        #pragma unroll
        for (int b = 0; b < B; ++b) {
            int t = b * NV + n;
            float gb = g_best[0][t];
            int   bi = g_bidx[0][t];
            #pragma unroll
            for (int c = 1; c < NCHUNK; ++c) {
                float v = g_best[c][t];
                int   vi = g_bidx[c][t];
                if (v < gb || (v == gb && vi < bi)) { gb = v; bi = vi; }
            }
            float4 p  = g_fn[b * NF + bi];
            float4 nm = g_nm[b * NF + bi];
            const float* q = cloth_n + ((long long)b * NV + n) * 3;
            float dx = __fsub_rn(q[0], p.x);
            float dy = __fsub_rn(q[1], p.y);
            float dz = __fsub_rn(q[2], p.z);
            float dist = __fmaf_rn(dz, nm.z, __fmaf_rn(dy, nm.y, __fmul_rn(dx, nm.x)));
            float t2 = __fsub_rn(1e-3f, dist);
            t2 = t2 > 0.0f ? t2 : 0.0f;
            acc = __fadd_rn(acc, __fmul_rn(__fmul_rn(t2, t2), t2));
        }
        val = __fmul_rn(__fmul_rn(acc, 0.5f), weight);
        out[1 + n] = val;
    }

    __shared__ float sh[256];
    sh[threadIdx.x] = val;
    __syncthreads();
    for (int k = 128; k > 0; k >>= 1) {
        if (threadIdx.x < k) sh[threadIdx.x] += sh[threadIdx.x + k];
        __syncthreads();
    }
    if (threadIdx.x == 0) g_partial[blockIdx.x] = sh[0];
}

// ---------------------------------------------------------------------------
// Kernel 4: out[0] = sum of 64 block partials (1 warp, deterministic)
// ---------------------------------------------------------------------------
__global__ void red_kernel(float* __restrict__ out) {
    int l = threadIdx.x;            // 32 threads
    float s = g_partial[l] + g_partial[l + 32];
    #pragma unroll
    for (int o = 16; o > 0; o >>= 1) s += __shfl_xor_sync(0xffffffffu, s, o);
    if (l == 0) out[0] = s;
}

// ---------------------------------------------------------------------------
// Resolve inputs BY SIZE (tolerant to elements-vs-bytes conventions)
// ---------------------------------------------------------------------------
extern "C" void kernel_launch(void* const* d_in, const int* in_sizes, int n_in,
                              void* d_out, int out_size) {
    const float* cloth_curr = nullptr;
    const float* cloth_next = nullptr;
    const float* obs_curr   = nullptr;
    const float* obs_next   = nullptr;
    const int*   faces32    = nullptr;
    const int*   iterp      = nullptr;

    int n_big = 0, n_obs = 0;
    for (int i = 0; i < n_in; ++i) {
        int s = in_sizes[i];
        if (s == 98304 || s == 393216) {
            if (n_big == 0)      cloth_curr = (const float*)d_in[i];
            else if (n_big == 1) cloth_next = (const float*)d_in[i];
            else                 faces32    = (const int*)d_in[i];
            ++n_big;
        } else if (s == 786432) {
            faces32 = (const int*)d_in[i];
        } else if (s == 72000 || s == 288000) {
            if (n_obs == 0) obs_curr = (const float*)d_in[i];
            else            obs_next = (const float*)d_in[i];
            ++n_obs;
        } else if (s == 1 || s == 4 || s == 8) {
            iterp = (const int*)d_in[i];
        }
    }

    float* out = (float*)d_out;

    prep_kernel<<<(B * NF + 255) / 256, 256>>>(obs_curr, obs_next, faces32);

    dim3 grid(NV / VPC, B, NCHUNK);   // (16, 2, 16) = 512 CTAs
    nn_kernel<<<grid, T2>>>(cloth_curr);

    epi_kernel<<<NV / 256, 256>>>(cloth_next, iterp, out);
    red_kernel<<<1, 32>>>(out);
}